// round 12
// baseline (speedup 1.0000x reference)
#include <cuda_runtime.h>

// S4D SSM layer, recurrence formulation of the FFT causal conv.
// Shapes hardcoded: L=4096, B=4, D=1024, N=16.
//
// pass0: per-d coefficient tables (packed f32x2 planes, coalesced loads later)
// pass1: complex local scan, TCHUNK=64 (grid 2048), MLP=8
// pass2: carry propagation across 64 chunks, blocked 4x16 reg-resident
// pass3: 2nd-order REAL recurrence u_i = a u_{i-1} + b u_{i-2} + pr x_i - g x_{i-1},
//        TCHUNK=64 (grid 2048), carry from chunk c-1, forced 5 CTAs/SM.

#define NSTATE 16
#define PACKS  8
#define TCH    64              // chunk for pass1 and pass3
#define LOG2_TCH 6
#define NCH    64              // L / TCH
#define D_DIM  1024
#define B_SZ   4
#define XS     (B_SZ * D_DIM)  // float stride per timestep = 4096
#define SCALE_F 0.25f

typedef unsigned long long ull;

__device__ __forceinline__ ull pack2(float lo, float hi) {
    ull r; asm("mov.b64 %0, {%1,%2};" : "=l"(r) : "f"(lo), "f"(hi)); return r;
}
__device__ __forceinline__ void unpack2(ull v, float& a, float& b) {
    asm("mov.b64 {%0,%1}, %2;" : "=f"(a), "=f"(b) : "l"(v));
}
__device__ __forceinline__ ull fma2(ull a, ull b, ull c) {
    ull d; asm("fma.rn.f32x2 %0, %1, %2, %3;" : "=l"(d) : "l"(a), "l"(b), "l"(c)); return d;
}
__device__ __forceinline__ ull mul2(ull a, ull b) {
    ull d; asm("mul.rn.f32x2 %0, %1, %2;" : "=l"(d) : "l"(a), "l"(b)); return d;
}
__device__ __forceinline__ ull add2(ull a, ull b) {
    ull d; asm("add.rn.f32x2 %0, %1, %2;" : "=l"(d) : "l"(a), "l"(b)); return d;
}

// chunk-boundary states: ((c*B + b)*NSTATE + n)*D + d  — coalesced in d
__device__ float2 g_state[1 << 22];   // 32 MB static scratch (64 chunks)

// coefficient tables, packed f32x2 per pack, [pack][d] layout (coalesced in d)
__device__ ull t_qr [PACKS][D_DIM];   // pass1: Re(q)
__device__ ull t_qi [PACKS][D_DIM];   //        Im(q)
__device__ ull t_nqi[PACKS][D_DIM];   //        -Im(q)
__device__ ull t_a  [PACKS][D_DIM];   // pass3: 2 Re(q)
__device__ ull t_b  [PACKS][D_DIM];   //        -|q|^2
__device__ ull t_pr [PACKS][D_DIM];   //        Re(p)
__device__ ull t_ng [PACKS][D_DIM];   //        -Re(p conj(q))
__device__ ull t_npi[PACKS][D_DIM];   //        -Im(p)
__device__ ull t_pqr[PACKS][D_DIM];   //        Re(p q)
__device__ ull t_npq[PACKS][D_DIM];   //        -Im(p q)

__device__ __forceinline__ float silu_of(float z) {
    float sg = __fdividef(1.0f, 1.0f + __expf(-z));
    return z * sg;
}

// ---------------------------------------------------------------------------
// pass0: one thread per d — compute all per-d coefficients, write tables.
// ---------------------------------------------------------------------------
__global__ void __launch_bounds__(128) s4d_pass0(
    const float* __restrict__ log_dt, const float* __restrict__ log_A_real,
    const float* __restrict__ A_imag, const float* __restrict__ Bparam,
    const float* __restrict__ Cparam)
{
    int d = blockIdx.x * 128 + threadIdx.x;
    float dt = __expf(log_dt[d]);

#pragma unroll
    for (int j = 0; j < PACKS; j++) {
        float qrv[2], qiv[2], av[2], bv[2], prv[2], ngv[2], npiv[2], pqrv[2], npqv[2];
#pragma unroll
        for (int k = 0; k < 2; k++) {
            int n = d * NSTATE + 2 * j + k;
            float zr = -0.5f * dt * __expf(log_A_real[n]);
            float zi =  0.5f * dt * A_imag[n];
            float omz = 1.0f - zr;
            float inv = __fdividef(1.0f, omz * omz + zi * zi);
            float qr = (1.0f - zr * zr - zi * zi) * inv;
            float qi = 2.0f * zi * inv;
            float Br = Bparam[n * 2 + 0];
            float Bi = Bparam[n * 2 + 1];
            float Cr = Cparam[n * 2 + 0];
            float Ci = Cparam[n * 2 + 1];
            float ccr = Br * Cr - Bi * Ci;
            float cci = Br * Ci + Bi * Cr;
            float w = dt * SCALE_F * inv;
            float pr = w * (ccr * omz - cci * zi);
            float pi = w * (ccr * zi + cci * omz);

            qrv[k]  = qr;
            qiv[k]  = qi;
            av[k]   = 2.0f * qr;
            bv[k]   = -(qr * qr + qi * qi);
            prv[k]  = pr;
            ngv[k]  = -(pr * qr + pi * qi);
            npiv[k] = -pi;
            pqrv[k] = pr * qr - pi * qi;
            npqv[k] = -(pr * qi + pi * qr);
        }
        t_qr [j][d] = pack2(qrv[0], qrv[1]);
        t_qi [j][d] = pack2(qiv[0], qiv[1]);
        t_nqi[j][d] = pack2(-qiv[0], -qiv[1]);
        t_a  [j][d] = pack2(av[0], av[1]);
        t_b  [j][d] = pack2(bv[0], bv[1]);
        t_pr [j][d] = pack2(prv[0], prv[1]);
        t_ng [j][d] = pack2(ngv[0], ngv[1]);
        t_npi[j][d] = pack2(npiv[0], npiv[1]);
        t_pqr[j][d] = pack2(pqrv[0], pqrv[1]);
        t_npq[j][d] = pack2(npqv[0], npqv[1]);
    }
}

// ---------------------------------------------------------------------------
// pass1: complex local scan, TCH=64, 1 thread per d, 8 loads/iter (MLP=8)
// ---------------------------------------------------------------------------
__global__ void __launch_bounds__(128, 6) s4d_pass1(const float* __restrict__ x)
{
    int d = blockIdx.x * 128 + threadIdx.x;
    int b = blockIdx.y;
    int c = blockIdx.z;

    ull Qr[PACKS], Qi[PACKS], nQi[PACKS], Sr[PACKS], Sm[PACKS];
#pragma unroll
    for (int j = 0; j < PACKS; j++) {
        Qr[j]  = t_qr [j][d];
        Qi[j]  = t_qi [j][d];
        nQi[j] = t_nqi[j][d];
        Sr[j] = 0ull; Sm[j] = 0ull;   // Sm holds m = -si
    }

    const float* xp = x + ((long long)(c * TCH) * B_SZ + b) * D_DIM + d;

    for (int it = 0; it < TCH / 8; it++) {
        float xv[8];
#pragma unroll
        for (int u = 0; u < 8; u++)
            xv[u] = xp[(long long)u * XS];
        xp += 8 * XS;

#pragma unroll
        for (int u = 0; u < 8; u++) {
            ull X2 = pack2(xv[u], xv[u]);
#pragma unroll
            for (int j = 0; j < PACKS; j++) {
                ull t   = fma2(Qi[j], Sm[j], X2);
                ull nsr = fma2(Qr[j], Sr[j], t);
                ull nm  = fma2(nQi[j], Sr[j], mul2(Qr[j], Sm[j]));
                Sr[j] = nsr; Sm[j] = nm;
            }
        }
    }

    float2* st = g_state + (((long long)c * B_SZ + b) * NSTATE) * D_DIM + d;
#pragma unroll
    for (int j = 0; j < PACKS; j++) {
        float r0, r1, m0, m1;
        unpack2(Sr[j], r0, r1); unpack2(Sm[j], m0, m1);
        st[(long long)(2*j    ) * D_DIM] = make_float2(r0, -m0);
        st[(long long)(2*j + 1) * D_DIM] = make_float2(r1, -m1);
    }
}

// ---------------------------------------------------------------------------
// pass2: carry scan over 64 chunks, blocked 4 x 16 (reg-resident, MLP=16)
// ---------------------------------------------------------------------------
__global__ void __launch_bounds__(256) s4d_pass2(
    const float* __restrict__ log_dt, const float* __restrict__ log_A_real,
    const float* __restrict__ A_imag)
{
    int id = blockIdx.x * 256 + threadIdx.x;
    int d = id % D_DIM;
    int n = (id / D_DIM) % NSTATE;
    int b = id / (D_DIM * NSTATE);

    float dt = __expf(log_dt[d]);
    float zr = -0.5f * dt * __expf(log_A_real[d * NSTATE + n]);
    float zi =  0.5f * dt * A_imag[d * NSTATE + n];
    float omz = 1.0f - zr;
    float inv = __fdividef(1.0f, omz * omz + zi * zi);
    float qr = (1.0f - zr * zr - zi * zi) * inv;
    float qi = 2.0f * zi * inv;

    // q^TCH via repeated squaring
#pragma unroll
    for (int i = 0; i < LOG2_TCH; i++) {
        float nr = qr * qr - qi * qi;
        float ni = 2.0f * qr * qi;
        qr = nr; qi = ni;
    }

    long long base = ((long long)b * NSTATE + n) * D_DIM + d;
    const long long cstride = (long long)B_SZ * NSTATE * D_DIM;

    float2 s = make_float2(0.0f, 0.0f);
#pragma unroll 1
    for (int blk = 0; blk < 4; blk++) {
        long long c0 = (long long)blk * 16;
        float2 t[16];
#pragma unroll
        for (int i = 0; i < 16; i++)
            t[i] = g_state[base + (c0 + i) * cstride];
#pragma unroll
        for (int i = 0; i < 16; i++) {
            float nr = fmaf(qr, s.x, fmaf(-qi, s.y, t[i].x));
            float ni = fmaf(qr, s.y, fmaf( qi, s.x, t[i].y));
            s.x = nr; s.y = ni;
            t[i] = s;
        }
#pragma unroll
        for (int i = 0; i < 16; i++)
            g_state[base + (c0 + i) * cstride] = t[i];
    }
}

// ---------------------------------------------------------------------------
// pass3: 2nd-order real recurrence on u = Re(p*s) + residual + silu.
// TCH=64; carry = end state of chunk c-1. Forced 5 CTAs/SM (<=102 regs).
// ---------------------------------------------------------------------------
__device__ __forceinline__ float rstep(const ull* A, const ull* Bc,
                                       const ull* Pr, const ull* nG,
                                       const ull* V, ull* VD,
                                       float xc, float xm)
{
    ull Xc = pack2(xc, xc);
    ull Xm = pack2(xm, xm);
    ull acc0 = 0ull, acc1 = 0ull;
#pragma unroll
    for (int j = 0; j < PACKS; j++) {
        ull w  = fma2(Pr[j], Xc, mul2(nG[j], Xm));
        ull t  = fma2(Bc[j], VD[j], w);
        ull nv = fma2(A[j], V[j], t);
        VD[j] = nv;
        if (j & 1) acc1 = add2(acc1, nv);
        else       acc0 = add2(acc0, nv);
    }
    ull s = add2(acc0, acc1);
    float lo, hi; unpack2(s, lo, hi);
    return lo + hi;
}

__global__ void __launch_bounds__(128, 5) s4d_pass3(
    const float* __restrict__ x, const float* __restrict__ Dparam,
    float* __restrict__ out)
{
    int d = blockIdx.x * 128 + threadIdx.x;
    int b = blockIdx.y;
    int c = blockIdx.z;

    const float* xp = x + ((long long)(c * TCH) * B_SZ + b) * D_DIM + d;
    float* op = out + ((long long)(c * TCH) * B_SZ + b) * D_DIM + d;
    float dpar = Dparam[d];

    float xs0 = xp[0];
    ull X0 = pack2(xs0, xs0);

    ull A[PACKS], Bc[PACKS], Pr[PACKS], nG[PACKS], U0[PACKS], U1[PACKS];

#pragma unroll
    for (int j = 0; j < PACKS; j++) {
        A[j]  = t_a [j][d];
        Bc[j] = t_b [j][d];
        Pr[j] = t_pr[j][d];
        nG[j] = t_ng[j][d];
    }

    ull yacc = 0ull;
    if (c > 0) {
        // carry = end state of chunk c-1
        const float2* st = g_state +
            (((long long)(c - 1) * B_SZ + b) * NSTATE) * D_DIM + d;
#pragma unroll
        for (int j = 0; j < PACKS; j++) {
            float2 v0 = st[(long long)(2*j    ) * D_DIM];
            float2 v1 = st[(long long)(2*j + 1) * D_DIM];
            ull Srp = pack2(v0.x, v1.x);
            ull Sip = pack2(v0.y, v1.y);
            // u_{-1} = Re(p s) = pr*sr - pi*si
            U1[j] = fma2(Pr[j], Srp, mul2(t_npi[j][d], Sip));
            // u_0 = Re(pq s) + pr*x0
            ull t = fma2(t_pqr[j][d], Srp, mul2(t_npq[j][d], Sip));
            U0[j] = fma2(Pr[j], X0, t);
            yacc = add2(yacc, U0[j]);
        }
    } else {
#pragma unroll
        for (int j = 0; j < PACKS; j++) {
            U1[j] = 0ull;
            U0[j] = mul2(Pr[j], X0);
            yacc = add2(yacc, U0[j]);
        }
    }
    {
        float lo, hi; unpack2(yacc, lo, hi);
        op[0] = silu_of(fmaf(xs0, dpar, lo + hi));
    }

    // step i = 1: V = U0 (u_0), VD = U1 (u_{-1}) -> U1 := u_1 (newest)
    float xm = xs0;
    {
        float xc = xp[XS];
        float y = rstep(A, Bc, Pr, nG, U0, U1, xc, xm);
        op[XS] = silu_of(fmaf(xc, dpar, y));
        xm = xc;
    }

    // steps i = 2..57: 7 groups of 8 (entering each group U1 = newest)
    const float* xq = xp + 2 * XS;
    float* oq = op + 2 * XS;
    for (int it = 0; it < 7; it++) {
        float xv[8];
#pragma unroll
        for (int u = 0; u < 8; u++)
            xv[u] = xq[(long long)u * XS];
        xq += 8 * XS;

#pragma unroll
        for (int u = 0; u < 8; u++) {
            float prev = (u == 0) ? xm : xv[u - 1];
            float y = (u & 1) ? rstep(A, Bc, Pr, nG, U0, U1, xv[u], prev)
                              : rstep(A, Bc, Pr, nG, U1, U0, xv[u], prev);
            oq[(long long)u * XS] = silu_of(fmaf(xv[u], dpar, y));
        }
        xm = xv[7];
        oq += 8 * XS;
    }

    // tail steps i = 58..63 (6 steps, entering U1 = newest)
    {
        float xv[6];
#pragma unroll
        for (int u = 0; u < 6; u++)
            xv[u] = xq[(long long)u * XS];

#pragma unroll
        for (int u = 0; u < 6; u++) {
            float prev = (u == 0) ? xm : xv[u - 1];
            float y = (u & 1) ? rstep(A, Bc, Pr, nG, U0, U1, xv[u], prev)
                              : rstep(A, Bc, Pr, nG, U1, U0, xv[u], prev);
            oq[(long long)u * XS] = silu_of(fmaf(xv[u], dpar, y));
        }
    }
}

extern "C" void kernel_launch(void* const* d_in, const int* in_sizes, int n_in,
                              void* d_out, int out_size)
{
    const float* x      = (const float*)d_in[0];
    const float* log_dt = (const float*)d_in[1];
    const float* lar    = (const float*)d_in[2];
    const float* aim    = (const float*)d_in[3];
    const float* Bp     = (const float*)d_in[4];
    const float* Cp     = (const float*)d_in[5];
    const float* Dp     = (const float*)d_in[6];
    float* out = (float*)d_out;

    s4d_pass0<<<D_DIM / 128, 128>>>(log_dt, lar, aim, Bp, Cp);

    dim3 blk(128);
    dim3 grd(D_DIM / 128, B_SZ, NCH);   // (8, 4, 64) = 2048 blocks

    s4d_pass1<<<grd, blk>>>(x);

    int total2 = B_SZ * NSTATE * D_DIM;      // 65536
    s4d_pass2<<<total2 / 256, 256>>>(log_dt, lar, aim);

    s4d_pass3<<<grd, blk>>>(x, Dp, out);
}

// round 13
// speedup vs baseline: 2.1055x; 2.1055x over previous
#include <cuda_runtime.h>

// S4D SSM layer, unified real-domain chunked scan.
// Shapes hardcoded: L=4096, B=4, D=1024, N=16.
//
// Per state n: u_i = a u_{i-1} + b u_{i-2} + pr x_i - g x_{i-1}
//   (a = 2 Re q, b = -|q|^2, pr = Re p, g = Re(p conj q); y = sum_n u_n)
//
// pass0: per-d coefficient tables (a, b, pr, -g) packed f32x2
// pass1: real local scan per chunk, zero-init pair, store (v_63, v_62)
// pass2: pair carry propagation across 64 chunks with companion C^64
// pass3: real scan with carried (u_{-1}, u_{-2}) init + output silu

#define NSTATE 16
#define PACKS  8
#define TCH    64
#define NCH    64              // L / TCH
#define D_DIM  1024
#define B_SZ   4
#define XS     (B_SZ * D_DIM)  // float stride per timestep = 4096
#define SCALE_F 0.25f

typedef unsigned long long ull;

__device__ __forceinline__ ull pack2(float lo, float hi) {
    ull r; asm("mov.b64 %0, {%1,%2};" : "=l"(r) : "f"(lo), "f"(hi)); return r;
}
__device__ __forceinline__ void unpack2(ull v, float& a, float& b) {
    asm("mov.b64 {%0,%1}, %2;" : "=f"(a), "=f"(b) : "l"(v));
}
__device__ __forceinline__ ull fma2(ull a, ull b, ull c) {
    ull d; asm("fma.rn.f32x2 %0, %1, %2, %3;" : "=l"(d) : "l"(a), "l"(b), "l"(c)); return d;
}
__device__ __forceinline__ ull mul2(ull a, ull b) {
    ull d; asm("mul.rn.f32x2 %0, %1, %2;" : "=l"(d) : "l"(a), "l"(b)); return d;
}
__device__ __forceinline__ ull add2(ull a, ull b) {
    ull d; asm("add.rn.f32x2 %0, %1, %2;" : "=l"(d) : "l"(a), "l"(b)); return d;
}

// chunk-boundary u pairs: ((c*B + b)*NSTATE + n)*D + d ; float2 = (u_last, u_last-1)
__device__ float2 g_state[1 << 22];   // 32 MB static scratch

// coefficient tables, packed f32x2 per pack, [pack][d] layout (coalesced in d)
__device__ ull t_a [PACKS][D_DIM];   // 2 Re(q)
__device__ ull t_b [PACKS][D_DIM];   // -|q|^2
__device__ ull t_pr[PACKS][D_DIM];   // Re(p)
__device__ ull t_ng[PACKS][D_DIM];   // -Re(p conj(q))

__device__ __forceinline__ float silu_of(float z) {
    float sg = __fdividef(1.0f, 1.0f + __expf(-z));
    return z * sg;
}

// ---------------------------------------------------------------------------
// pass0: one thread per d — compute per-d coefficients, write tables.
// ---------------------------------------------------------------------------
__global__ void __launch_bounds__(128) s4d_pass0(
    const float* __restrict__ log_dt, const float* __restrict__ log_A_real,
    const float* __restrict__ A_imag, const float* __restrict__ Bparam,
    const float* __restrict__ Cparam)
{
    int d = blockIdx.x * 128 + threadIdx.x;
    float dt = __expf(log_dt[d]);

#pragma unroll
    for (int j = 0; j < PACKS; j++) {
        float av[2], bv[2], prv[2], ngv[2];
#pragma unroll
        for (int k = 0; k < 2; k++) {
            int n = d * NSTATE + 2 * j + k;
            float zr = -0.5f * dt * __expf(log_A_real[n]);
            float zi =  0.5f * dt * A_imag[n];
            float omz = 1.0f - zr;
            float inv = __fdividef(1.0f, omz * omz + zi * zi);
            float qr = (1.0f - zr * zr - zi * zi) * inv;
            float qi = 2.0f * zi * inv;
            float Br = Bparam[n * 2 + 0];
            float Bi = Bparam[n * 2 + 1];
            float Cr = Cparam[n * 2 + 0];
            float Ci = Cparam[n * 2 + 1];
            float ccr = Br * Cr - Bi * Ci;
            float cci = Br * Ci + Bi * Cr;
            float w = dt * SCALE_F * inv;
            float pr = w * (ccr * omz - cci * zi);
            float pi = w * (ccr * zi + cci * omz);

            av[k]  = 2.0f * qr;
            bv[k]  = -(qr * qr + qi * qi);
            prv[k] = pr;
            ngv[k] = -(pr * qr + pi * qi);
        }
        t_a [j][d] = pack2(av[0], av[1]);
        t_b [j][d] = pack2(bv[0], bv[1]);
        t_pr[j][d] = pack2(prv[0], prv[1]);
        t_ng[j][d] = pack2(ngv[0], ngv[1]);
    }
}

// one recurrence step over all packs: VD := A*V + Bc*VD + Pr*xc + nG*xm
__device__ __forceinline__ void pstep(const ull* A, const ull* Bc,
                                      const ull* Pr, const ull* nG,
                                      const ull* V, ull* VD,
                                      float xc, float xm)
{
    ull Xc = pack2(xc, xc);
    ull Xm = pack2(xm, xm);
#pragma unroll
    for (int j = 0; j < PACKS; j++) {
        ull w = fma2(Pr[j], Xc, mul2(nG[j], Xm));
        ull t = fma2(Bc[j], VD[j], w);
        VD[j] = fma2(A[j], V[j], t);
    }
}

// step with reduction: returns sum over all 16 states of the new u
__device__ __forceinline__ float rstep(const ull* A, const ull* Bc,
                                       const ull* Pr, const ull* nG,
                                       const ull* V, ull* VD,
                                       float xc, float xm)
{
    ull Xc = pack2(xc, xc);
    ull Xm = pack2(xm, xm);
    ull acc0 = 0ull, acc1 = 0ull;
#pragma unroll
    for (int j = 0; j < PACKS; j++) {
        ull w  = fma2(Pr[j], Xc, mul2(nG[j], Xm));
        ull t  = fma2(Bc[j], VD[j], w);
        ull nv = fma2(A[j], V[j], t);
        VD[j] = nv;
        if (j & 1) acc1 = add2(acc1, nv);
        else       acc0 = add2(acc0, nv);
    }
    ull s = add2(acc0, acc1);
    float lo, hi; unpack2(s, lo, hi);
    return lo + hi;
}

// ---------------------------------------------------------------------------
// pass1: real local scan, zero-init pair, TCH=64, MLP=8.
// After 64 steps (even), newest v_63 sits in U0, v_62 in U1.
// ---------------------------------------------------------------------------
__global__ void __launch_bounds__(128) s4d_pass1(const float* __restrict__ x)
{
    int d = blockIdx.x * 128 + threadIdx.x;
    int b = blockIdx.y;
    int c = blockIdx.z;

    ull A[PACKS], Bc[PACKS], Pr[PACKS], nG[PACKS], U0[PACKS], U1[PACKS];
#pragma unroll
    for (int j = 0; j < PACKS; j++) {
        A[j]  = t_a [j][d];
        Bc[j] = t_b [j][d];
        Pr[j] = t_pr[j][d];
        nG[j] = t_ng[j][d];
        U0[j] = 0ull; U1[j] = 0ull;
    }

    long long base = ((long long)(c * TCH) * B_SZ + b) * D_DIM + d;
    float xm = (c == 0) ? 0.0f : x[base - XS];
    const float* xq = x + base;

    for (int it = 0; it < 8; it++) {
        float xv[8];
#pragma unroll
        for (int u = 0; u < 8; u++)
            xv[u] = xq[(long long)u * XS];
        xq += 8 * XS;

#pragma unroll
        for (int u = 0; u < 8; u++) {
            float prev = (u == 0) ? xm : xv[u - 1];
            if (u & 1) pstep(A, Bc, Pr, nG, U1, U0, xv[u], prev);
            else       pstep(A, Bc, Pr, nG, U0, U1, xv[u], prev);
        }
        xm = xv[7];
    }

    float2* st = g_state + (((long long)c * B_SZ + b) * NSTATE) * D_DIM + d;
#pragma unroll
    for (int j = 0; j < PACKS; j++) {
        float n0, n1, p0, p1;
        unpack2(U0[j], n0, n1);   // v_63
        unpack2(U1[j], p0, p1);   // v_62
        st[(long long)(2*j    ) * D_DIM] = make_float2(n0, p0);
        st[(long long)(2*j + 1) * D_DIM] = make_float2(n1, p1);
    }
}

// ---------------------------------------------------------------------------
// pass2: pair carry propagation with companion C^64, blocked 4x16.
// ---------------------------------------------------------------------------
__global__ void __launch_bounds__(256) s4d_pass2(
    const float* __restrict__ log_dt, const float* __restrict__ log_A_real,
    const float* __restrict__ A_imag)
{
    int id = blockIdx.x * 256 + threadIdx.x;
    int d = id % D_DIM;
    int n = (id / D_DIM) % NSTATE;
    int b = id / (D_DIM * NSTATE);

    float dt = __expf(log_dt[d]);
    float zr = -0.5f * dt * __expf(log_A_real[d * NSTATE + n]);
    float zi =  0.5f * dt * A_imag[d * NSTATE + n];
    float omz = 1.0f - zr;
    float inv = __fdividef(1.0f, omz * omz + zi * zi);
    float qr = (1.0f - zr * zr - zi * zi) * inv;
    float qi = 2.0f * zi * inv;

    // companion C = [[a, b],[1,0]]; M = C^64 via 6 squarings
    float m00 = 2.0f * qr, m01 = -(qr * qr + qi * qi);
    float m10 = 1.0f, m11 = 0.0f;
#pragma unroll
    for (int i = 0; i < 6; i++) {
        float n00 = m00 * m00 + m01 * m10;
        float n01 = m00 * m01 + m01 * m11;
        float n10 = m10 * m00 + m11 * m10;
        float n11 = m10 * m01 + m11 * m11;
        m00 = n00; m01 = n01; m10 = n10; m11 = n11;
    }

    long long base = ((long long)b * NSTATE + n) * D_DIM + d;
    const long long cstride = (long long)B_SZ * NSTATE * D_DIM;

    float tx = 0.0f, ty = 0.0f;   // carried true pair (u_last, u_last-1)
#pragma unroll 1
    for (int blk = 0; blk < 4; blk++) {
        long long c0 = (long long)blk * 16;
        float2 t[16];
#pragma unroll
        for (int i = 0; i < 16; i++)
            t[i] = g_state[base + (c0 + i) * cstride];
#pragma unroll
        for (int i = 0; i < 16; i++) {
            float nx = fmaf(m00, tx, fmaf(m01, ty, t[i].x));
            float ny = fmaf(m10, tx, fmaf(m11, ty, t[i].y));
            tx = nx; ty = ny;
            t[i] = make_float2(tx, ty);
        }
#pragma unroll
        for (int i = 0; i < 16; i++)
            g_state[base + (c0 + i) * cstride] = t[i];
    }
}

// ---------------------------------------------------------------------------
// pass3: real scan with carried (u_{-1}, u_{-2}) init, output silu.
// Uniform 8 groups of 8 steps; carry = pair of chunk c-1.
// ---------------------------------------------------------------------------
__global__ void __launch_bounds__(128) s4d_pass3(
    const float* __restrict__ x, const float* __restrict__ Dparam,
    float* __restrict__ out)
{
    int d = blockIdx.x * 128 + threadIdx.x;
    int b = blockIdx.y;
    int c = blockIdx.z;

    long long base = ((long long)(c * TCH) * B_SZ + b) * D_DIM + d;
    const float* xq = x + base;
    float* oq = out + base;
    float dpar = Dparam[d];

    ull A[PACKS], Bc[PACKS], Pr[PACKS], nG[PACKS], U0[PACKS], U1[PACKS];
#pragma unroll
    for (int j = 0; j < PACKS; j++) {
        A[j]  = t_a [j][d];
        Bc[j] = t_b [j][d];
        Pr[j] = t_pr[j][d];
        nG[j] = t_ng[j][d];
    }

    float xm;
    if (c > 0) {
        const float2* st = g_state +
            (((long long)(c - 1) * B_SZ + b) * NSTATE) * D_DIM + d;
#pragma unroll
        for (int j = 0; j < PACKS; j++) {
            float2 v0 = st[(long long)(2*j    ) * D_DIM];
            float2 v1 = st[(long long)(2*j + 1) * D_DIM];
            U0[j] = pack2(v0.x, v1.x);   // u_{-1}
            U1[j] = pack2(v0.y, v1.y);   // u_{-2}
        }
        xm = x[base - XS];
    } else {
#pragma unroll
        for (int j = 0; j < PACKS; j++) { U0[j] = 0ull; U1[j] = 0ull; }
        xm = 0.0f;
    }

    for (int it = 0; it < 8; it++) {
        float xv[8];
#pragma unroll
        for (int u = 0; u < 8; u++)
            xv[u] = xq[(long long)u * XS];
        xq += 8 * XS;

#pragma unroll
        for (int u = 0; u < 8; u++) {
            float prev = (u == 0) ? xm : xv[u - 1];
            float y = (u & 1) ? rstep(A, Bc, Pr, nG, U1, U0, xv[u], prev)
                              : rstep(A, Bc, Pr, nG, U0, U1, xv[u], prev);
            oq[(long long)u * XS] = silu_of(fmaf(xv[u], dpar, y));
        }
        xm = xv[7];
        oq += 8 * XS;
    }
}

extern "C" void kernel_launch(void* const* d_in, const int* in_sizes, int n_in,
                              void* d_out, int out_size)
{
    const float* x      = (const float*)d_in[0];
    const float* log_dt = (const float*)d_in[1];
    const float* lar    = (const float*)d_in[2];
    const float* aim    = (const float*)d_in[3];
    const float* Bp     = (const float*)d_in[4];
    const float* Cp     = (const float*)d_in[5];
    const float* Dp     = (const float*)d_in[6];
    float* out = (float*)d_out;

    s4d_pass0<<<D_DIM / 128, 128>>>(log_dt, lar, aim, Bp, Cp);

    dim3 blk(128);
    dim3 grd(D_DIM / 128, B_SZ, NCH);   // (8, 4, 64) = 2048 blocks

    s4d_pass1<<<grd, blk>>>(x);

    int total2 = B_SZ * NSTATE * D_DIM;      // 65536
    s4d_pass2<<<total2 / 256, 256>>>(log_dt, lar, aim);

    s4d_pass3<<<grd, blk>>>(x, Dp, out);
}

// round 14
// speedup vs baseline: 2.2379x; 1.0629x over previous
#include <cuda_runtime.h>

// S4D SSM layer, unified real-domain chunked scan + cp.async x staging.
// Shapes hardcoded: L=4096, B=4, D=1024, N=16.
//
// Per state n: u_i = a u_{i-1} + b u_{i-2} + pr x_i - g x_{i-1}
// pass0: per-d coefficient tables (a, b, pr, -g) packed f32x2
// pass1: real local scan per chunk (zero init), cp.async-staged x
// pass2: pair carry propagation across 64 chunks with companion C^64
// pass3: real scan with carried (u_{-1}, u_{-2}) init + silu, cp.async-staged x

#define NSTATE 16
#define PACKS  8
#define TCH    64
#define NCH    64              // L / TCH
#define D_DIM  1024
#define B_SZ   4
#define XS     (B_SZ * D_DIM)  // float stride per timestep = 4096
#define SCALE_F 0.25f

typedef unsigned long long ull;

__device__ __forceinline__ ull pack2(float lo, float hi) {
    ull r; asm("mov.b64 %0, {%1,%2};" : "=l"(r) : "f"(lo), "f"(hi)); return r;
}
__device__ __forceinline__ void unpack2(ull v, float& a, float& b) {
    asm("mov.b64 {%0,%1}, %2;" : "=f"(a), "=f"(b) : "l"(v));
}
__device__ __forceinline__ ull fma2(ull a, ull b, ull c) {
    ull d; asm("fma.rn.f32x2 %0, %1, %2, %3;" : "=l"(d) : "l"(a), "l"(b), "l"(c)); return d;
}
__device__ __forceinline__ ull mul2(ull a, ull b) {
    ull d; asm("mul.rn.f32x2 %0, %1, %2;" : "=l"(d) : "l"(a), "l"(b)); return d;
}
__device__ __forceinline__ ull add2(ull a, ull b) {
    ull d; asm("add.rn.f32x2 %0, %1, %2;" : "=l"(d) : "l"(a), "l"(b)); return d;
}

__device__ __forceinline__ unsigned smem_u32(const void* p) {
    unsigned a;
    asm("{ .reg .u64 t; cvta.to.shared.u64 t, %1; cvt.u32.u64 %0, t; }"
        : "=r"(a) : "l"(p));
    return a;
}
__device__ __forceinline__ void cp4(unsigned s, const float* g) {
    asm volatile("cp.async.ca.shared.global [%0], [%1], 4;" :: "r"(s), "l"(g));
}
__device__ __forceinline__ void cp_commit() { asm volatile("cp.async.commit_group;"); }
__device__ __forceinline__ void cp_wait1()  { asm volatile("cp.async.wait_group 1;"); }
__device__ __forceinline__ void cp_wait0()  { asm volatile("cp.async.wait_group 0;"); }

// chunk-boundary u pairs: ((c*B + b)*NSTATE + n)*D + d ; float2 = (u_last, u_last-1)
__device__ float2 g_state[1 << 22];   // 32 MB static scratch

// coefficient tables, packed f32x2 per pack, [pack][d] layout (coalesced in d)
__device__ ull t_a [PACKS][D_DIM];   // 2 Re(q)
__device__ ull t_b [PACKS][D_DIM];   // -|q|^2
__device__ ull t_pr[PACKS][D_DIM];   // Re(p)
__device__ ull t_ng[PACKS][D_DIM];   // -Re(p conj(q))

__device__ __forceinline__ float silu_of(float z) {
    float sg = __fdividef(1.0f, 1.0f + __expf(-z));
    return z * sg;
}

// ---------------------------------------------------------------------------
// pass0: one thread per d — compute per-d coefficients, write tables.
// ---------------------------------------------------------------------------
__global__ void __launch_bounds__(128) s4d_pass0(
    const float* __restrict__ log_dt, const float* __restrict__ log_A_real,
    const float* __restrict__ A_imag, const float* __restrict__ Bparam,
    const float* __restrict__ Cparam)
{
    int d = blockIdx.x * 128 + threadIdx.x;
    float dt = __expf(log_dt[d]);

#pragma unroll
    for (int j = 0; j < PACKS; j++) {
        float av[2], bv[2], prv[2], ngv[2];
#pragma unroll
        for (int k = 0; k < 2; k++) {
            int n = d * NSTATE + 2 * j + k;
            float zr = -0.5f * dt * __expf(log_A_real[n]);
            float zi =  0.5f * dt * A_imag[n];
            float omz = 1.0f - zr;
            float inv = __fdividef(1.0f, omz * omz + zi * zi);
            float qr = (1.0f - zr * zr - zi * zi) * inv;
            float qi = 2.0f * zi * inv;
            float Br = Bparam[n * 2 + 0];
            float Bi = Bparam[n * 2 + 1];
            float Cr = Cparam[n * 2 + 0];
            float Ci = Cparam[n * 2 + 1];
            float ccr = Br * Cr - Bi * Ci;
            float cci = Br * Ci + Bi * Cr;
            float w = dt * SCALE_F * inv;
            float pr = w * (ccr * omz - cci * zi);
            float pi = w * (ccr * zi + cci * omz);

            av[k]  = 2.0f * qr;
            bv[k]  = -(qr * qr + qi * qi);
            prv[k] = pr;
            ngv[k] = -(pr * qr + pi * qi);
        }
        t_a [j][d] = pack2(av[0], av[1]);
        t_b [j][d] = pack2(bv[0], bv[1]);
        t_pr[j][d] = pack2(prv[0], prv[1]);
        t_ng[j][d] = pack2(ngv[0], ngv[1]);
    }
}

// one recurrence step over all packs: VD := A*V + Bc*VD + Pr*xc + nG*xm
__device__ __forceinline__ void pstep(const ull* A, const ull* Bc,
                                      const ull* Pr, const ull* nG,
                                      const ull* V, ull* VD,
                                      float xc, float xm)
{
    ull Xc = pack2(xc, xc);
    ull Xm = pack2(xm, xm);
#pragma unroll
    for (int j = 0; j < PACKS; j++) {
        ull w = fma2(Pr[j], Xc, mul2(nG[j], Xm));
        ull t = fma2(Bc[j], VD[j], w);
        VD[j] = fma2(A[j], V[j], t);
    }
}

// step with reduction: returns sum over all 16 states of the new u
__device__ __forceinline__ float rstep(const ull* A, const ull* Bc,
                                       const ull* Pr, const ull* nG,
                                       const ull* V, ull* VD,
                                       float xc, float xm)
{
    ull Xc = pack2(xc, xc);
    ull Xm = pack2(xm, xm);
    ull acc0 = 0ull, acc1 = 0ull;
#pragma unroll
    for (int j = 0; j < PACKS; j++) {
        ull w  = fma2(Pr[j], Xc, mul2(nG[j], Xm));
        ull t  = fma2(Bc[j], VD[j], w);
        ull nv = fma2(A[j], V[j], t);
        VD[j] = nv;
        if (j & 1) acc1 = add2(acc1, nv);
        else       acc0 = add2(acc0, nv);
    }
    ull s = add2(acc0, acc1);
    float lo, hi; unpack2(s, lo, hi);
    return lo + hi;
}

// ---------------------------------------------------------------------------
// pass1: real local scan, zero-init pair, cp.async double-buffered x.
// ---------------------------------------------------------------------------
__global__ void __launch_bounds__(128) s4d_pass1(const float* __restrict__ x)
{
    __shared__ float sx[2][8 * 128];
    int t = threadIdx.x;
    int d = blockIdx.x * 128 + t;
    int b = blockIdx.y;
    int c = blockIdx.z;

    ull A[PACKS], Bc[PACKS], Pr[PACKS], nG[PACKS], U0[PACKS], U1[PACKS];
#pragma unroll
    for (int j = 0; j < PACKS; j++) {
        A[j]  = t_a [j][d];
        Bc[j] = t_b [j][d];
        Pr[j] = t_pr[j][d];
        nG[j] = t_ng[j][d];
        U0[j] = 0ull; U1[j] = 0ull;
    }

    long long base = ((long long)(c * TCH) * B_SZ + b) * D_DIM + d;
    float xm = (c == 0) ? 0.0f : x[base - XS];
    const float* xg = x + base;

    unsigned sb0 = smem_u32(&sx[0][0]) + t * 4;
    unsigned sb1 = smem_u32(&sx[1][0]) + t * 4;

    // prologue: stage group 0 into buffer 0
#pragma unroll
    for (int u = 0; u < 8; u++)
        cp4(sb0 + u * 512, xg + (long long)u * XS);
    cp_commit();
    xg += 8 * XS;

    for (int it = 0; it < 8; it++) {
        if (it < 7) {
            unsigned sb = ((it + 1) & 1) ? sb1 : sb0;
#pragma unroll
            for (int u = 0; u < 8; u++)
                cp4(sb + u * 512, xg + (long long)u * XS);
            cp_commit();
            xg += 8 * XS;
            cp_wait1();
        } else {
            cp_wait0();
        }

        const float* sc = (it & 1) ? &sx[1][0] : &sx[0][0];
#pragma unroll
        for (int u = 0; u < 8; u++) {
            float xc = sc[u * 128 + t];
            if (u & 1) pstep(A, Bc, Pr, nG, U1, U0, xc, xm);
            else       pstep(A, Bc, Pr, nG, U0, U1, xc, xm);
            xm = xc;
        }
    }

    float2* st = g_state + (((long long)c * B_SZ + b) * NSTATE) * D_DIM + d;
#pragma unroll
    for (int j = 0; j < PACKS; j++) {
        float n0, n1, p0, p1;
        unpack2(U0[j], n0, n1);   // v_63
        unpack2(U1[j], p0, p1);   // v_62
        st[(long long)(2*j    ) * D_DIM] = make_float2(n0, p0);
        st[(long long)(2*j + 1) * D_DIM] = make_float2(n1, p1);
    }
}

// ---------------------------------------------------------------------------
// pass2: pair carry propagation with companion C^64, blocked 4x16.
// ---------------------------------------------------------------------------
__global__ void __launch_bounds__(256) s4d_pass2(
    const float* __restrict__ log_dt, const float* __restrict__ log_A_real,
    const float* __restrict__ A_imag)
{
    int id = blockIdx.x * 256 + threadIdx.x;
    int d = id % D_DIM;
    int n = (id / D_DIM) % NSTATE;
    int b = id / (D_DIM * NSTATE);

    float dt = __expf(log_dt[d]);
    float zr = -0.5f * dt * __expf(log_A_real[d * NSTATE + n]);
    float zi =  0.5f * dt * A_imag[d * NSTATE + n];
    float omz = 1.0f - zr;
    float inv = __fdividef(1.0f, omz * omz + zi * zi);
    float qr = (1.0f - zr * zr - zi * zi) * inv;
    float qi = 2.0f * zi * inv;

    // companion C = [[a, b],[1,0]]; M = C^64 via 6 squarings
    float m00 = 2.0f * qr, m01 = -(qr * qr + qi * qi);
    float m10 = 1.0f, m11 = 0.0f;
#pragma unroll
    for (int i = 0; i < 6; i++) {
        float n00 = m00 * m00 + m01 * m10;
        float n01 = m00 * m01 + m01 * m11;
        float n10 = m10 * m00 + m11 * m10;
        float n11 = m10 * m01 + m11 * m11;
        m00 = n00; m01 = n01; m10 = n10; m11 = n11;
    }

    long long base = ((long long)b * NSTATE + n) * D_DIM + d;
    const long long cstride = (long long)B_SZ * NSTATE * D_DIM;

    float tx = 0.0f, ty = 0.0f;   // carried true pair (u_last, u_last-1)
#pragma unroll 1
    for (int blk = 0; blk < 4; blk++) {
        long long c0 = (long long)blk * 16;
        float2 t[16];
#pragma unroll
        for (int i = 0; i < 16; i++)
            t[i] = g_state[base + (c0 + i) * cstride];
#pragma unroll
        for (int i = 0; i < 16; i++) {
            float nx = fmaf(m00, tx, fmaf(m01, ty, t[i].x));
            float ny = fmaf(m10, tx, fmaf(m11, ty, t[i].y));
            tx = nx; ty = ny;
            t[i] = make_float2(tx, ty);
        }
#pragma unroll
        for (int i = 0; i < 16; i++)
            g_state[base + (c0 + i) * cstride] = t[i];
    }
}

// ---------------------------------------------------------------------------
// pass3: real scan with carried (u_{-1}, u_{-2}) init, silu output,
// cp.async double-buffered x.
// ---------------------------------------------------------------------------
__global__ void __launch_bounds__(128) s4d_pass3(
    const float* __restrict__ x, const float* __restrict__ Dparam,
    float* __restrict__ out)
{
    __shared__ float sx[2][8 * 128];
    int t = threadIdx.x;
    int d = blockIdx.x * 128 + t;
    int b = blockIdx.y;
    int c = blockIdx.z;

    long long base = ((long long)(c * TCH) * B_SZ + b) * D_DIM + d;
    const float* xg = x + base;
    float* oq = out + base;
    float dpar = Dparam[d];

    unsigned sb0 = smem_u32(&sx[0][0]) + t * 4;
    unsigned sb1 = smem_u32(&sx[1][0]) + t * 4;

    // stage group 0 immediately (overlaps with coefficient/carry loads)
#pragma unroll
    for (int u = 0; u < 8; u++)
        cp4(sb0 + u * 512, xg + (long long)u * XS);
    cp_commit();
    xg += 8 * XS;

    ull A[PACKS], Bc[PACKS], Pr[PACKS], nG[PACKS], U0[PACKS], U1[PACKS];
#pragma unroll
    for (int j = 0; j < PACKS; j++) {
        A[j]  = t_a [j][d];
        Bc[j] = t_b [j][d];
        Pr[j] = t_pr[j][d];
        nG[j] = t_ng[j][d];
    }

    float xm;
    if (c > 0) {
        const float2* st = g_state +
            (((long long)(c - 1) * B_SZ + b) * NSTATE) * D_DIM + d;
#pragma unroll
        for (int j = 0; j < PACKS; j++) {
            float2 v0 = st[(long long)(2*j    ) * D_DIM];
            float2 v1 = st[(long long)(2*j + 1) * D_DIM];
            U0[j] = pack2(v0.x, v1.x);   // u_{-1}
            U1[j] = pack2(v0.y, v1.y);   // u_{-2}
        }
        xm = x[base - XS];
    } else {
#pragma unroll
        for (int j = 0; j < PACKS; j++) { U0[j] = 0ull; U1[j] = 0ull; }
        xm = 0.0f;
    }

    for (int it = 0; it < 8; it++) {
        if (it < 7) {
            unsigned sb = ((it + 1) & 1) ? sb1 : sb0;
#pragma unroll
            for (int u = 0; u < 8; u++)
                cp4(sb + u * 512, xg + (long long)u * XS);
            cp_commit();
            xg += 8 * XS;
            cp_wait1();
        } else {
            cp_wait0();
        }

        const float* sc = (it & 1) ? &sx[1][0] : &sx[0][0];
#pragma unroll
        for (int u = 0; u < 8; u++) {
            float xc = sc[u * 128 + t];
            float y = (u & 1) ? rstep(A, Bc, Pr, nG, U1, U0, xc, xm)
                              : rstep(A, Bc, Pr, nG, U0, U1, xc, xm);
            oq[(long long)u * XS] = silu_of(fmaf(xc, dpar, y));
            xm = xc;
        }
        oq += 8 * XS;
    }
}

extern "C" void kernel_launch(void* const* d_in, const int* in_sizes, int n_in,
                              void* d_out, int out_size)
{
    const float* x      = (const float*)d_in[0];
    const float* log_dt = (const float*)d_in[1];
    const float* lar    = (const float*)d_in[2];
    const float* aim    = (const float*)d_in[3];
    const float* Bp     = (const float*)d_in[4];
    const float* Cp     = (const float*)d_in[5];
    const float* Dp     = (const float*)d_in[6];
    float* out = (float*)d_out;

    s4d_pass0<<<D_DIM / 128, 128>>>(log_dt, lar, aim, Bp, Cp);

    dim3 blk(128);
    dim3 grd(D_DIM / 128, B_SZ, NCH);   // (8, 4, 64) = 2048 blocks

    s4d_pass1<<<grd, blk>>>(x);

    int total2 = B_SZ * NSTATE * D_DIM;      // 65536
    s4d_pass2<<<total2 / 256, 256>>>(log_dt, lar, aim);

    s4d_pass3<<<grd, blk>>>(x, Dp, out);
}